// round 10
// baseline (speedup 1.0000x reference)
#include <cuda_runtime.h>
#include <math.h>

// Problem constants (match reference)
#define Bn 8
#define Nn 1000
#define Cn 81
#define CR (Cn-1)
#define Kn 100
#define Mn 28
#define MM (Mn*Mn)
#define IMG_W 1216.0f
#define IMG_H 800.0f
#define SCORE_THRESH 0.05f
#define NMS_THRESH 0.5f
#define BBOX_CLIP 4.135166556742356f   // log(1000/16)
#define SLOT 1024                       // per-class NMS smem capacity (m <= 1000)
#define TSEL 2048                       // top-k selection smem cap
#define RANK_MAX 512                    // rank-select path cap
#define CAPI (CR*Nn)                    // per-image candidate capacity (worst case)

// Output layout: concat of [B,K,4] boxes, [B,K] scores, [B,K] labels, [B,K,1,M,M] masks (all f32)
#define OFF_B 0
#define OFF_S (Bn*Kn*4)
#define OFF_L (OFF_S + Bn*Kn)
#define OFF_M (OFF_L + Bn*Kn)

// ---------------- scratch (device globals; zero-initialized at load) --------
__device__ int   g_cls_m[Bn*CR];                       // above-threshold count per (b,class)
__device__ unsigned long long g_cls_key[Bn*CR*Nn];     // packed (score_bits<<32 | ~n)
__device__ int   g_img_count[Bn];                      // NMS survivors per image
__device__ int   g_done_img[Bn];                       // per-image NMS-block completion counter
__device__ float g_cand_score[Bn*CAPI];
__device__ int   g_cand_flat [Bn*CAPI];
__device__ float4 g_cand_box [Bn*CAPI];
__device__ int   g_labels[Bn*Kn];
__device__ unsigned long long g_fb_key[Bn*CAPI];       // exact fallback only

// ---------------- kernel 1: softmax + threshold-filter append ----------------
__device__ __forceinline__ void append_cand(int b, int cr, int n, float s) {
    int idx = b*CR + cr;
    int p = atomicAdd(&g_cls_m[idx], 1);   // p < Nn guaranteed (one per (cr,n))
    g_cls_key[(size_t)idx*Nn + p] =
        ((unsigned long long)__float_as_uint(s) << 32)
      | (unsigned long long)(0xFFFFFFFFu - (unsigned)n);
}

__global__ void k_softmax(const float* __restrict__ logits) {
    int w = (blockIdx.x * blockDim.x + threadIdx.x) >> 5;   // global warp = row
    if (w >= Bn*Nn) return;
    int lane = threadIdx.x & 31;

    const float* rowp = logits + (size_t)w * Cn;
    float v0 = rowp[lane];                                     // classes 0..31
    float v1 = rowp[32 + lane];                                // classes 32..63
    float v2 = (64 + lane < Cn) ? rowp[64 + lane] : -INFINITY; // classes 64..80

    float m = fmaxf(v0, fmaxf(v1, v2));
    #pragma unroll
    for (int off = 16; off > 0; off >>= 1)
        m = fmaxf(m, __shfl_xor_sync(0xFFFFFFFFu, m, off));

    float e0 = expf(v0 - m);
    float e1 = expf(v1 - m);
    float e2 = (64 + lane < Cn) ? expf(v2 - m) : 0.0f;
    float s = e0 + e1 + e2;
    #pragma unroll
    for (int off = 16; off > 0; off >>= 1)
        s += __shfl_xor_sync(0xFFFFFFFFu, s, off);

    int b = w / Nn;
    int n = w % Nn;

    float s0 = e0 / s;
    float s1 = e1 / s;
    if (lane >= 1 && s0 > SCORE_THRESH)        append_cand(b, lane - 1,  n, s0);
    if (s1 > SCORE_THRESH)                      append_cand(b, 31 + lane, n, s1);
    if (64 + lane < Cn) {
        float s2 = e2 / s;
        if (s2 > SCORE_THRESH)                  append_cand(b, 63 + lane, n, s2);
    }
}

// ---------------- kernel 2: NMS per (b,class); last block per image does topK
// grid = B*CR, block = 128
union SMu {
    struct {
        unsigned long long key[SLOT];   // 8 KB
        float4 box[SLOT];               // 16 KB
        float  area[SLOT];              // 4 KB
        unsigned char keep[SLOT];       // 1 KB
        short sidx[SLOT];               // 2 KB
    } n;                                // 31 KB
    struct {
        int hist[4096];                 // 16 KB
        unsigned long long skey[TSEL];  // 16 KB
        int spay[TSEL];                 // 8 KB
    } t;                                // 40 KB
};

__global__ void __launch_bounds__(128) k_nms_topk(const float* __restrict__ reg,
                                                  const float* __restrict__ props,
                                                  float* __restrict__ out) {
    int pair = blockIdx.x;
    int b  = pair / CR;
    int cr = pair % CR;
    int cc = cr + 1;
    int tid = threadIdx.x;
    int lane = tid & 31;
    int wid = tid >> 5;

    __shared__ SMu sm;
    __shared__ int scntS, baseS, lastS, p_sh, nsel_sh, cc_sh;
    __shared__ int wsum[4], wexcl[4];

    // ================= phase 1: per-(b,class) NMS =================
    int m = g_cls_m[b*CR + cr];          // uniform read
    if (m > Nn) m = Nn;

    if (m > 0) {
        __syncthreads();                 // reads complete before re-arm
        if (tid == 0) { g_cls_m[b*CR + cr] = 0; scntS = 0; }

        const unsigned long long* kk = g_cls_key + (size_t)(b*CR + cr)*Nn;
        for (int i = tid; i < m; i += 128) sm.n.key[i] = kk[i];

        int sn = 1; while (sn < m) sn <<= 1; if (sn < 2) sn = 2;
        for (int i = m + tid; i < sn; i += 128) sm.n.key[i] = 0ULL;
        __syncthreads();

        // bitonic sort DESCENDING
        for (int k = 2; k <= sn; k <<= 1) {
            for (int j = k >> 1; j > 0; j >>= 1) {
                for (int i = tid; i < sn; i += 128) {
                    int ixj = i ^ j;
                    if (ixj > i) {
                        unsigned long long a = sm.n.key[i], bb = sm.n.key[ixj];
                        bool up = ((i & k) == 0);
                        if (up ? (a < bb) : (a > bb)) { sm.n.key[i] = bb; sm.n.key[ixj] = a; }
                    }
                }
                __syncthreads();
            }
        }

        // decode + clip boxes
        for (int i = tid; i < m; i += 128) {
            unsigned orig = 0xFFFFFFFFu - (unsigned)(sm.n.key[i] & 0xFFFFFFFFull);
            int row = b*Nn + (int)orig;
            float px1 = props[row*4+0], py1 = props[row*4+1];
            float px2 = props[row*4+2], py2 = props[row*4+3];
            float w = px2 - px1, h = py2 - py1;
            float cx = px1 + 0.5f*w, cy = py1 + 0.5f*h;
            const float* r = reg + (size_t)row*Cn*4 + cc*4;
            float dx = r[0] / 10.0f;
            float dy = r[1] / 10.0f;
            float dw = fminf(r[2] / 5.0f, BBOX_CLIP);
            float dh = fminf(r[3] / 5.0f, BBOX_CLIP);
            float pcx = dx*w + cx;
            float pcy = dy*h + cy;
            float pw = expf(dw)*w;
            float ph = expf(dh)*h;
            float x1 = pcx - 0.5f*pw, y1 = pcy - 0.5f*ph;
            float x2 = pcx + 0.5f*pw, y2 = pcy + 0.5f*ph;
            x1 = fminf(fmaxf(x1, 0.0f), IMG_W);
            y1 = fminf(fmaxf(y1, 0.0f), IMG_H);
            x2 = fminf(fmaxf(x2, 0.0f), IMG_W);
            y2 = fminf(fmaxf(y2, 0.0f), IMG_H);
            float4 bv; bv.x = x1; bv.y = y1; bv.z = x2; bv.w = y2;
            sm.n.box[i] = bv;
            sm.n.area[i] = (x2 - x1) * (y2 - y1);
            sm.n.keep[i] = 1;
        }
        __syncthreads();

        // sequential greedy suppression
        for (int i = 0; i < m; ++i) {
            __syncthreads();
            if (!sm.n.keep[i]) continue;        // uniform after barrier
            float4 bi = sm.n.box[i];
            float ai = sm.n.area[i];
            for (int j = i + 1 + tid; j < m; j += 128) {
                float4 bj = sm.n.box[j];
                float lx = fmaxf(bi.x, bj.x);
                float ly = fmaxf(bi.y, bj.y);
                float rx = fminf(bi.z, bj.z);
                float ry = fminf(bi.w, bj.w);
                float iw = fmaxf(rx - lx, 0.0f);
                float ih = fmaxf(ry - ly, 0.0f);
                float inter = iw * ih;
                float iou = inter / (ai + sm.n.area[j] - inter + 1e-9f);
                if (iou > NMS_THRESH) sm.n.keep[j] = 0;
            }
        }
        __syncthreads();

        // collect survivors, reserve contiguous chunk in per-image list
        for (int i = tid; i < m; i += 128) {
            if (sm.n.keep[i]) sm.n.sidx[atomicAdd(&scntS, 1)] = (short)i;
        }
        __syncthreads();
        if (tid == 0) baseS = atomicAdd(&g_img_count[b], scntS);
        __syncthreads();
        int cnt = scntS, base = baseS;
        for (int j = tid; j < cnt; j += 128) {
            int i = sm.n.sidx[j];
            int o = b*CAPI + base + j;
            g_cand_score[o] = __uint_as_float((unsigned)(sm.n.key[i] >> 32));
            g_cand_flat[o]  = cr*Nn + i;
            g_cand_box[o]   = sm.n.box[i];
        }
    }

    // ================= phase 2: last block of image b runs top-K =============
    __threadfence();                     // publish this block's g_cand writes
    __syncthreads();
    if (tid == 0) lastS = (atomicAdd(&g_done_img[b], 1) == CR - 1);
    __syncthreads();
    if (!lastS) return;
    __threadfence();                     // acquire peers' writes
    if (tid == 0) g_done_img[b] = 0;     // re-arm for next replay

    int V = g_img_count[b];              // uniform read
    if (V > CAPI) V = CAPI;
    __syncthreads();                     // reads before re-arm + smem union reuse
    if (tid == 0) { g_img_count[b] = 0; p_sh = 0; cc_sh = 0; }
    for (int i = tid; i < 4096; i += 128) sm.t.hist[i] = 0;
    __syncthreads();

    // histogram top-12 score bits
    for (int j = tid; j < V; j += 128) {
        unsigned bits = __float_as_uint(g_cand_score[b*CAPI + j]);
        atomicAdd(&sm.t.hist[bits >> 20], 1);
    }
    __syncthreads();

    // suffix sums: per-thread chunk of 32 bins; warp suffix + 4-warp combine
    int csum = 0;
    #pragma unroll
    for (int q = 0; q < 32; ++q) csum += sm.t.hist[tid*32 + q];
    int val = csum;
    #pragma unroll
    for (int off = 1; off < 32; off <<= 1) {
        int v = __shfl_down_sync(0xFFFFFFFFu, val, off);
        if (lane + off < 32) val += v;
    }
    if (lane == 0) wsum[wid] = val;
    __syncthreads();
    if (tid == 0) {
        int t = 0;
        for (int w = 3; w >= 0; --w) { wexcl[w] = t; t += wsum[w]; }
        nsel_sh = t;
    }
    __syncthreads();
    int suf_incl = val + wexcl[wid];
    int suf_excl = suf_incl - csum;
    // unique crossing thread finds pivot p = max bin with S(bin) >= K
    if (suf_excl < Kn && suf_incl >= Kn) {
        int running = suf_excl;
        for (int q = 31; q >= 0; --q) {
            int bin = tid*32 + q;
            running += sm.t.hist[bin];
            if (running >= Kn) { p_sh = bin; nsel_sh = running; break; }
        }
    }
    __syncthreads();
    int p = p_sh;
    int nsel = nsel_sh;

    if (nsel <= TSEL) {
        // compact selected candidates
        for (int j = tid; j < V; j += 128) {
            int o = b*CAPI + j;
            unsigned bits = __float_as_uint(g_cand_score[o]);
            if ((int)(bits >> 20) >= p) {
                int pos = atomicAdd(&cc_sh, 1);
                unsigned flat = (unsigned)g_cand_flat[o];
                sm.t.skey[pos] = ((unsigned long long)bits << 17)
                               | (unsigned long long)(0x1FFFFu - flat);
                sm.t.spay[pos] = j;
            }
        }
        __syncthreads();

        if (nsel <= RANK_MAX) {
            // rank-based selection (keys unique -> exact permutation)
            for (int i = tid; i < nsel; i += 128) {
                unsigned long long mykey = sm.t.skey[i];
                int rank = 0;
                for (int j = 0; j < nsel; ++j)
                    rank += (sm.t.skey[j] > mykey) ? 1 : 0;
                if (rank < Kn) {
                    int d = b*Kn + rank;
                    int o = b*CAPI + sm.t.spay[i];
                    float s   = g_cand_score[o];
                    int flat  = g_cand_flat[o];
                    int lab   = flat / Nn + 1;
                    float4 bx = g_cand_box[o];
                    out[OFF_B + d*4 + 0] = bx.x;
                    out[OFF_B + d*4 + 1] = bx.y;
                    out[OFF_B + d*4 + 2] = bx.z;
                    out[OFF_B + d*4 + 3] = bx.w;
                    out[OFF_S + d] = s;
                    out[OFF_L + d] = (float)lab;
                    g_labels[d] = lab;
                }
            }
            // zero-fill slots [nsel, K)
            for (int k = nsel + tid; k < Kn; k += 128) {
                int d = b*Kn + k;
                out[OFF_B + d*4 + 0] = 0.0f;
                out[OFF_B + d*4 + 1] = 0.0f;
                out[OFF_B + d*4 + 2] = 0.0f;
                out[OFF_B + d*4 + 3] = 0.0f;
                out[OFF_S + d] = 0.0f;
                out[OFF_L + d] = 0.0f;
                g_labels[d] = 0;
            }
            return;
        }

        // bitonic path for 512 < nsel <= 2048
        int sn = 1; while (sn < nsel) sn <<= 1; if (sn < 2) sn = 2;
        for (int i = nsel + tid; i < sn; i += 128) sm.t.skey[i] = 0ULL;
        __syncthreads();
        for (int k = 2; k <= sn; k <<= 1) {
            for (int j = k >> 1; j > 0; j >>= 1) {
                for (int i = tid; i < sn; i += 128) {
                    int ixj = i ^ j;
                    if (ixj > i) {
                        unsigned long long a = sm.t.skey[i], bb = sm.t.skey[ixj];
                        bool up = ((i & k) == 0);
                        if (up ? (a < bb) : (a > bb)) {
                            sm.t.skey[i] = bb; sm.t.skey[ixj] = a;
                            int t2 = sm.t.spay[i]; sm.t.spay[i] = sm.t.spay[ixj]; sm.t.spay[ixj] = t2;
                        }
                    }
                }
                __syncthreads();
            }
        }
        for (int k = tid; k < Kn; k += 128) {
            int d = b*Kn + k;
            unsigned long long v = sm.t.skey[k];
            if (k < nsel && v != 0ULL) {
                int o = b*CAPI + sm.t.spay[k];
                float s   = g_cand_score[o];
                int flat  = g_cand_flat[o];
                int lab   = flat / Nn + 1;
                float4 bx = g_cand_box[o];
                out[OFF_B + d*4 + 0] = bx.x;
                out[OFF_B + d*4 + 1] = bx.y;
                out[OFF_B + d*4 + 2] = bx.z;
                out[OFF_B + d*4 + 3] = bx.w;
                out[OFF_S + d] = s;
                out[OFF_L + d] = (float)lab;
                g_labels[d] = lab;
            } else {
                out[OFF_B + d*4 + 0] = 0.0f;
                out[OFF_B + d*4 + 1] = 0.0f;
                out[OFF_B + d*4 + 2] = 0.0f;
                out[OFF_B + d*4 + 3] = 0.0f;
                out[OFF_S + d] = 0.0f;
                out[OFF_L + d] = 0.0f;
                g_labels[d] = 0;
            }
        }
        return;
    }

    // ---------- exact fallback (pathological tie storm): destructive argmax ----------
    for (int j = tid; j < V; j += 128) {
        int o = b*CAPI + j;
        unsigned bits = __float_as_uint(g_cand_score[o]);
        unsigned flat = (unsigned)g_cand_flat[o];
        g_fb_key[o] = ((unsigned long long)bits << 17)
                    | (unsigned long long)(0x1FFFFu - flat);
    }
    __syncthreads();
    __shared__ unsigned long long rk[128];
    __shared__ int ri[128];
    for (int k = 0; k < Kn; ++k) {
        unsigned long long bk = 0ULL; int bj = -1;
        for (int j = tid; j < V; j += 128) {
            unsigned long long v = g_fb_key[b*CAPI + j];
            if (v > bk) { bk = v; bj = j; }
        }
        rk[tid] = bk; ri[tid] = bj;
        __syncthreads();
        for (int s = 64; s > 0; s >>= 1) {
            if (tid < s && rk[tid+s] > rk[tid]) { rk[tid] = rk[tid+s]; ri[tid] = ri[tid+s]; }
            __syncthreads();
        }
        if (tid == 0) {
            int d = b*Kn + k;
            if (rk[0] != 0ULL) {
                int o = b*CAPI + ri[0];
                float s  = g_cand_score[o];
                int flat = g_cand_flat[o];
                int lab  = flat / Nn + 1;
                float4 bx = g_cand_box[o];
                out[OFF_B + d*4 + 0] = bx.x;
                out[OFF_B + d*4 + 1] = bx.y;
                out[OFF_B + d*4 + 2] = bx.z;
                out[OFF_B + d*4 + 3] = bx.w;
                out[OFF_S + d] = s;
                out[OFF_L + d] = (float)lab;
                g_labels[d] = lab;
                g_fb_key[o] = 0ULL;
            } else {
                out[OFF_B + d*4 + 0] = 0.0f;
                out[OFF_B + d*4 + 1] = 0.0f;
                out[OFF_B + d*4 + 2] = 0.0f;
                out[OFF_B + d*4 + 3] = 0.0f;
                out[OFF_S + d] = 0.0f;
                out[OFF_L + d] = 0.0f;
                g_labels[d] = 0;
            }
        }
        __syncthreads();
    }
}

// ---------------- kernel 3: mask gather + sigmoid, 1 float4/thread ----------
// grid = ceil(800*196/256), block = 256; no smem, no barriers
__global__ void k_mask(const float* __restrict__ ml, float* __restrict__ out) {
    const int Q4 = MM/4;                 // 196 float4 per det
    int idx = blockIdx.x * blockDim.x + threadIdx.x;
    if (idx >= Bn*Kn*Q4) return;
    int d = idx / Q4;
    int q = idx - d*Q4;
    int lab = g_labels[d];               // L2-broadcast across the 196 threads of det d
    float4 x = ((const float4*)(ml + ((size_t)d*Cn + lab)*MM))[q];
    float4 pv;
    pv.x = (x.x >= 0.0f) ? 1.0f/(1.0f + expf(-x.x)) : expf(x.x)/(1.0f + expf(x.x));
    pv.y = (x.y >= 0.0f) ? 1.0f/(1.0f + expf(-x.y)) : expf(x.y)/(1.0f + expf(x.y));
    pv.z = (x.z >= 0.0f) ? 1.0f/(1.0f + expf(-x.z)) : expf(x.z)/(1.0f + expf(x.z));
    pv.w = (x.w >= 0.0f) ? 1.0f/(1.0f + expf(-x.w)) : expf(x.w)/(1.0f + expf(x.w));
    ((float4*)(out + OFF_M))[idx] = pv;
}

extern "C" void kernel_launch(void* const* d_in, const int* in_sizes, int n_in,
                              void* d_out, int out_size) {
    const float* logits = (const float*)d_in[0];   // [B*N, C]
    const float* reg    = (const float*)d_in[1];   // [B*N, C*4]
    const float* props  = (const float*)d_in[2];   // [B, N, 4]
    const float* ml     = (const float*)d_in[3];   // [B, K, C, M, M]
    float* out = (float*)d_out;

    k_softmax<<<(Bn*Nn*32 + 255)/256, 256>>>(logits);
    k_nms_topk<<<Bn*CR, 128>>>(reg, props, out);
    k_mask<<<(Bn*Kn*(MM/4) + 255)/256, 256>>>(ml, out);
}

// round 11
// speedup vs baseline: 1.1021x; 1.1021x over previous
#include <cuda_runtime.h>
#include <math.h>

// Problem constants (match reference)
#define Bn 8
#define Nn 1000
#define Cn 81
#define CR (Cn-1)
#define Kn 100
#define Mn 28
#define MM (Mn*Mn)
#define IMG_W 1216.0f
#define IMG_H 800.0f
#define SCORE_THRESH 0.05f
#define NMS_THRESH 0.5f
#define BBOX_CLIP 4.135166556742356f   // log(1000/16)
#define SLOT 1024                       // per-class NMS smem capacity (m <= 1000)
#define TSEL 2048                       // top-k selection smem cap
#define RANK_MAX 512                    // rank-select path cap
#define CAPI (CR*Nn)                    // per-image candidate capacity (worst case)

// Output layout: concat of [B,K,4] boxes, [B,K] scores, [B,K] labels, [B,K,1,M,M] masks (all f32)
#define OFF_B 0
#define OFF_S (Bn*Kn*4)
#define OFF_L (OFF_S + Bn*Kn)
#define OFF_M (OFF_L + Bn*Kn)

// ---------------- scratch (device globals; zero-initialized at load) --------
__device__ int   g_cls_m[Bn*CR];                       // above-threshold count per (b,class)
__device__ unsigned long long g_cls_key[Bn*CR*Nn];     // packed (score_bits<<32 | ~n)
__device__ int   g_img_count[Bn];                      // NMS survivors per image
__device__ float g_cand_score[Bn*CAPI];
__device__ int   g_cand_flat [Bn*CAPI];
__device__ float4 g_cand_box [Bn*CAPI];
__device__ int   g_labels[Bn*Kn];
__device__ unsigned long long g_fb_key[Bn*CAPI];       // exact fallback only

// ---------------- kernel 1: softmax + threshold-filter append ----------------
// 2 rows per warp: two independent latency chains per scheduler slot (ILP=2)
__device__ __forceinline__ void append_cand(int b, int cr, int n, float s) {
    int idx = b*CR + cr;
    int p = atomicAdd(&g_cls_m[idx], 1);   // p < Nn guaranteed (one per (cr,n))
    g_cls_key[(size_t)idx*Nn + p] =
        ((unsigned long long)__float_as_uint(s) << 32)
      | (unsigned long long)(0xFFFFFFFFu - (unsigned)n);
}

__global__ void k_softmax(const float* __restrict__ logits) {
    int wpair = (blockIdx.x * blockDim.x + threadIdx.x) >> 5;   // warp = 2 rows
    int row0 = wpair * 2;
    if (row0 >= Bn*Nn) return;
    int lane = threadIdx.x & 31;

    #pragma unroll
    for (int r = 0; r < 2; ++r) {
        int w = row0 + r;                                        // row index
        const float* rowp = logits + (size_t)w * Cn;
        float v0 = rowp[lane];                                     // classes 0..31
        float v1 = rowp[32 + lane];                                // classes 32..63
        float v2 = (64 + lane < Cn) ? rowp[64 + lane] : -INFINITY; // classes 64..80

        float m = fmaxf(v0, fmaxf(v1, v2));
        #pragma unroll
        for (int off = 16; off > 0; off >>= 1)
            m = fmaxf(m, __shfl_xor_sync(0xFFFFFFFFu, m, off));

        float e0 = expf(v0 - m);
        float e1 = expf(v1 - m);
        float e2 = (64 + lane < Cn) ? expf(v2 - m) : 0.0f;
        float s = e0 + e1 + e2;
        #pragma unroll
        for (int off = 16; off > 0; off >>= 1)
            s += __shfl_xor_sync(0xFFFFFFFFu, s, off);

        int b = w / Nn;
        int n = w % Nn;

        float s0 = e0 / s;
        float s1 = e1 / s;
        if (lane >= 1 && s0 > SCORE_THRESH)        append_cand(b, lane - 1,  n, s0);
        if (s1 > SCORE_THRESH)                      append_cand(b, 31 + lane, n, s1);
        if (64 + lane < Cn) {
            float s2 = e2 / s;
            if (s2 > SCORE_THRESH)                  append_cand(b, 63 + lane, n, s2);
        }
    }
}

// ---------------- kernel 2: sort -> decode -> NMS per (b,class) ----
// grid = B*CR, block = 128 (latency hiding for global gather phases)
__global__ void k_nms(const float* __restrict__ reg,
                      const float* __restrict__ props) {
    int pair = blockIdx.x;
    int b  = pair / CR;
    int cr = pair % CR;
    int cc = cr + 1;
    int tid = threadIdx.x;

    __shared__ unsigned long long key[SLOT];
    __shared__ float4 box[SLOT];
    __shared__ float  area[SLOT];
    __shared__ unsigned char keep[SLOT];
    __shared__ short sidx[SLOT];
    __shared__ int scntS, baseS;

    int m = g_cls_m[b*CR + cr];          // all threads read (same insn, pre-branch)
    if (m > Nn) m = Nn;
    if (m == 0) return;
    __syncthreads();                     // all reads complete before re-arm write
    if (tid == 0) { g_cls_m[b*CR + cr] = 0; scntS = 0; }   // re-arm for next replay

    // load pre-filtered keys
    const unsigned long long* kk = g_cls_key + (size_t)(b*CR + cr)*Nn;
    for (int i = tid; i < m; i += blockDim.x) key[i] = kk[i];

    // pad to next pow2
    int sn = 1; while (sn < m) sn <<= 1; if (sn < 2) sn = 2;
    for (int i = m + tid; i < sn; i += blockDim.x) key[i] = 0ULL;
    __syncthreads();

    // bitonic sort DESCENDING over sn keys
    for (int k = 2; k <= sn; k <<= 1) {
        for (int j = k >> 1; j > 0; j >>= 1) {
            for (int i = tid; i < sn; i += blockDim.x) {
                int ixj = i ^ j;
                if (ixj > i) {
                    unsigned long long a = key[i], bb = key[ixj];
                    bool up = ((i & k) == 0);
                    if (up ? (a < bb) : (a > bb)) { key[i] = bb; key[ixj] = a; }
                }
            }
            __syncthreads();
        }
    }

    // decode + clip boxes for the m sorted candidates
    for (int i = tid; i < m; i += blockDim.x) {
        unsigned orig = 0xFFFFFFFFu - (unsigned)(key[i] & 0xFFFFFFFFull);
        int row = b*Nn + (int)orig;
        float px1 = props[row*4+0], py1 = props[row*4+1];
        float px2 = props[row*4+2], py2 = props[row*4+3];
        float w = px2 - px1, h = py2 - py1;
        float cx = px1 + 0.5f*w, cy = py1 + 0.5f*h;
        const float* r = reg + (size_t)row*Cn*4 + cc*4;
        float dx = r[0] / 10.0f;
        float dy = r[1] / 10.0f;
        float dw = fminf(r[2] / 5.0f, BBOX_CLIP);
        float dh = fminf(r[3] / 5.0f, BBOX_CLIP);
        float pcx = dx*w + cx;
        float pcy = dy*h + cy;
        float pw = expf(dw)*w;
        float ph = expf(dh)*h;
        float x1 = pcx - 0.5f*pw, y1 = pcy - 0.5f*ph;
        float x2 = pcx + 0.5f*pw, y2 = pcy + 0.5f*ph;
        x1 = fminf(fmaxf(x1, 0.0f), IMG_W);
        y1 = fminf(fmaxf(y1, 0.0f), IMG_H);
        x2 = fminf(fmaxf(x2, 0.0f), IMG_W);
        y2 = fminf(fmaxf(y2, 0.0f), IMG_H);
        float4 bv; bv.x = x1; bv.y = y1; bv.z = x2; bv.w = y2;
        box[i] = bv;
        area[i] = (x2 - x1) * (y2 - y1);
        keep[i] = 1;
    }
    __syncthreads();

    // sequential greedy suppression
    for (int i = 0; i < m; ++i) {
        __syncthreads();
        if (!keep[i]) continue;            // uniform after barrier
        float4 bi = box[i];
        float ai = area[i];
        for (int j = i + 1 + tid; j < m; j += blockDim.x) {
            float4 bj = box[j];
            float lx = fmaxf(bi.x, bj.x);
            float ly = fmaxf(bi.y, bj.y);
            float rx = fminf(bi.z, bj.z);
            float ry = fminf(bi.w, bj.w);
            float iw = fmaxf(rx - lx, 0.0f);
            float ih = fmaxf(ry - ly, 0.0f);
            float inter = iw * ih;
            float iou = inter / (ai + area[j] - inter + 1e-9f);
            if (iou > NMS_THRESH) keep[j] = 0;
        }
    }
    __syncthreads();

    // collect survivor indices, reserve contiguous chunk in per-image list
    for (int i = tid; i < m; i += blockDim.x) {
        if (keep[i]) sidx[atomicAdd(&scntS, 1)] = (short)i;
    }
    __syncthreads();
    if (tid == 0) baseS = atomicAdd(&g_img_count[b], scntS);
    __syncthreads();
    int cnt = scntS, base = baseS;
    for (int j = tid; j < cnt; j += blockDim.x) {
        int i = sidx[j];
        int o = b*CAPI + base + j;
        g_cand_score[o] = __uint_as_float((unsigned)(key[i] >> 32));
        g_cand_flat[o]  = cr*Nn + i;     // flat index into per-class sorted layout
        g_cand_box[o]   = box[i];
    }
}

// ---------------- kernel 3: per-image top-K via radix-select + rank ----
// grid = B, block = 512; dense candidate list; shuffle-based suffix scan
__global__ void k_topk(float* __restrict__ out) {
    int b = blockIdx.x;
    int tid = threadIdx.x;
    int lane = tid & 31;
    int wid = tid >> 5;
    int V = g_img_count[b];
    if (V > CAPI) V = CAPI;
    __syncthreads();                       // ALL threads read V before re-arm
    if (tid == 0) g_img_count[b] = 0;      // re-arm for next replay

    __shared__ int hist[4096];       // 12-bit score-bit bins
    __shared__ int wsum[16], wexcl[16];
    __shared__ unsigned long long skey[TSEL];
    __shared__ int spay[TSEL];
    __shared__ int p_sh, nsel_sh, cc_sh;

    for (int i = tid; i < 4096; i += 512) hist[i] = 0;
    if (tid == 0) { p_sh = 0; cc_sh = 0; }
    __syncthreads();

    // pass 1: histogram top-12 score bits (dense, coalesced)
    for (int j = tid; j < V; j += 512) {
        unsigned bits = __float_as_uint(g_cand_score[b*CAPI + j]);
        atomicAdd(&hist[bits >> 20], 1);
    }
    __syncthreads();

    // suffix sums via 2-level shuffle scan (suf_incl(t) = sum_{t'>=t} csum(t'))
    int csum = 0;
    #pragma unroll
    for (int q = 0; q < 8; ++q) csum += hist[tid*8 + q];
    int val = csum;
    #pragma unroll
    for (int off = 1; off < 32; off <<= 1) {
        int v = __shfl_down_sync(0xFFFFFFFFu, val, off);
        if (lane + off < 32) val += v;
    }
    if (lane == 0) wsum[wid] = val;      // warp total
    __syncthreads();
    if (tid < 16) {
        int t = wsum[tid];
        int sfx = t;
        #pragma unroll
        for (int off = 1; off < 16; off <<= 1) {
            int v = __shfl_down_sync(0x0000FFFFu, sfx, off);
            if (tid + off < 16) sfx += v;
        }
        wexcl[tid] = sfx - t;            // sum over warps > tid
        if (tid == 0) nsel_sh = sfx;     // grand total
    }
    __syncthreads();
    int suf_incl = val + wexcl[wid];
    int suf_excl = suf_incl - csum;
    // unique crossing thread finds pivot p = max bin with S(bin) >= K
    if (suf_excl < Kn && suf_incl >= Kn) {
        int running = suf_excl;
        for (int q = 7; q >= 0; --q) {
            int bin = tid*8 + q;
            running += hist[bin];
            if (running >= Kn) { p_sh = bin; nsel_sh = running; break; }
        }
    }
    __syncthreads();
    int p = p_sh;
    int nsel = nsel_sh;

    if (nsel <= TSEL) {
        // pass 2: compact selected candidates (dense, coalesced)
        for (int j = tid; j < V; j += 512) {
            int o = b*CAPI + j;
            unsigned bits = __float_as_uint(g_cand_score[o]);
            if ((int)(bits >> 20) >= p) {
                int pos = atomicAdd(&cc_sh, 1);
                unsigned flat = (unsigned)g_cand_flat[o];
                skey[pos] = ((unsigned long long)bits << 17)
                          | (unsigned long long)(0x1FFFFu - flat);
                spay[pos] = j;
            }
        }
        __syncthreads();

        if (nsel <= RANK_MAX) {
            // rank-based selection: keys unique -> exact permutation
            if (tid < nsel) {
                unsigned long long mykey = skey[tid];
                int rank = 0;
                for (int j = 0; j < nsel; ++j)
                    rank += (skey[j] > mykey) ? 1 : 0;
                if (rank < Kn) {
                    int d = b*Kn + rank;
                    int o = b*CAPI + spay[tid];
                    float s   = g_cand_score[o];
                    int flat  = g_cand_flat[o];
                    int lab   = flat / Nn + 1;
                    float4 bx = g_cand_box[o];
                    out[OFF_B + d*4 + 0] = bx.x;
                    out[OFF_B + d*4 + 1] = bx.y;
                    out[OFF_B + d*4 + 2] = bx.z;
                    out[OFF_B + d*4 + 3] = bx.w;
                    out[OFF_S + d] = s;
                    out[OFF_L + d] = (float)lab;
                    g_labels[d] = lab;
                }
            }
            // zero-fill slots [nsel, K)
            if (tid >= nsel && tid < Kn) {
                int d = b*Kn + tid;
                out[OFF_B + d*4 + 0] = 0.0f;
                out[OFF_B + d*4 + 1] = 0.0f;
                out[OFF_B + d*4 + 2] = 0.0f;
                out[OFF_B + d*4 + 3] = 0.0f;
                out[OFF_S + d] = 0.0f;
                out[OFF_L + d] = 0.0f;
                g_labels[d] = 0;
            }
            return;
        }

        // bitonic path for larger nsel
        int sn = 1; while (sn < nsel) sn <<= 1; if (sn < 2) sn = 2;
        for (int i = nsel + tid; i < sn; i += 512) skey[i] = 0ULL;
        __syncthreads();
        for (int k = 2; k <= sn; k <<= 1) {
            for (int j = k >> 1; j > 0; j >>= 1) {
                for (int i = tid; i < sn; i += 512) {
                    int ixj = i ^ j;
                    if (ixj > i) {
                        unsigned long long a = skey[i], bb = skey[ixj];
                        bool up = ((i & k) == 0);
                        if (up ? (a < bb) : (a > bb)) {
                            skey[i] = bb; skey[ixj] = a;
                            int t2 = spay[i]; spay[i] = spay[ixj]; spay[ixj] = t2;
                        }
                    }
                }
                __syncthreads();
            }
        }
        if (tid < Kn) {
            int d = b*Kn + tid;
            unsigned long long v = skey[tid];
            if (tid < nsel && v != 0ULL) {
                int o = b*CAPI + spay[tid];
                float s   = g_cand_score[o];
                int flat  = g_cand_flat[o];
                int lab   = flat / Nn + 1;
                float4 bx = g_cand_box[o];
                out[OFF_B + d*4 + 0] = bx.x;
                out[OFF_B + d*4 + 1] = bx.y;
                out[OFF_B + d*4 + 2] = bx.z;
                out[OFF_B + d*4 + 3] = bx.w;
                out[OFF_S + d] = s;
                out[OFF_L + d] = (float)lab;
                g_labels[d] = lab;
            } else {
                out[OFF_B + d*4 + 0] = 0.0f;
                out[OFF_B + d*4 + 1] = 0.0f;
                out[OFF_B + d*4 + 2] = 0.0f;
                out[OFF_B + d*4 + 3] = 0.0f;
                out[OFF_S + d] = 0.0f;
                out[OFF_L + d] = 0.0f;
                g_labels[d] = 0;
            }
        }
        return;
    }

    // ---------- exact fallback (pathological tie storm): destructive argmax ----------
    for (int j = tid; j < V; j += 512) {
        int o = b*CAPI + j;
        unsigned bits = __float_as_uint(g_cand_score[o]);
        unsigned flat = (unsigned)g_cand_flat[o];
        g_fb_key[o] = ((unsigned long long)bits << 17)
                    | (unsigned long long)(0x1FFFFu - flat);
    }
    __syncthreads();
    __shared__ unsigned long long rk[512];
    __shared__ int ri[512];
    for (int k = 0; k < Kn; ++k) {
        unsigned long long bk = 0ULL; int bj = -1;
        for (int j = tid; j < V; j += 512) {
            unsigned long long v = g_fb_key[b*CAPI + j];
            if (v > bk) { bk = v; bj = j; }
        }
        rk[tid] = bk; ri[tid] = bj;
        __syncthreads();
        for (int s = 256; s > 0; s >>= 1) {
            if (tid < s && rk[tid+s] > rk[tid]) { rk[tid] = rk[tid+s]; ri[tid] = ri[tid+s]; }
            __syncthreads();
        }
        if (tid == 0) {
            int d = b*Kn + k;
            if (rk[0] != 0ULL) {
                int o = b*CAPI + ri[0];
                float s  = g_cand_score[o];
                int flat = g_cand_flat[o];
                int lab  = flat / Nn + 1;
                float4 bx = g_cand_box[o];
                out[OFF_B + d*4 + 0] = bx.x;
                out[OFF_B + d*4 + 1] = bx.y;
                out[OFF_B + d*4 + 2] = bx.z;
                out[OFF_B + d*4 + 3] = bx.w;
                out[OFF_S + d] = s;
                out[OFF_L + d] = (float)lab;
                g_labels[d] = lab;
                g_fb_key[o] = 0ULL;
            } else {
                out[OFF_B + d*4 + 0] = 0.0f;
                out[OFF_B + d*4 + 1] = 0.0f;
                out[OFF_B + d*4 + 2] = 0.0f;
                out[OFF_B + d*4 + 3] = 0.0f;
                out[OFF_S + d] = 0.0f;
                out[OFF_L + d] = 0.0f;
                g_labels[d] = 0;
            }
        }
        __syncthreads();
    }
}

// ---------------- kernel 4: mask gather + sigmoid, 1 float2/thread ----------
// grid = ceil(800*392/256) = 1225, block = 256; max thread-level parallelism
__global__ void k_mask(const float* __restrict__ ml, float* __restrict__ out) {
    const int Q2 = MM/2;                 // 392 float2 per det
    int idx = blockIdx.x * blockDim.x + threadIdx.x;
    if (idx >= Bn*Kn*Q2) return;
    int d = idx / Q2;
    int q = idx - d*Q2;
    int lab = g_labels[d];               // L2-broadcast across the 392 threads of det d
    float2 x = ((const float2*)(ml + ((size_t)d*Cn + lab)*MM))[q];
    float2 pv;
    pv.x = (x.x >= 0.0f) ? 1.0f/(1.0f + expf(-x.x)) : expf(x.x)/(1.0f + expf(x.x));
    pv.y = (x.y >= 0.0f) ? 1.0f/(1.0f + expf(-x.y)) : expf(x.y)/(1.0f + expf(x.y));
    ((float2*)(out + OFF_M))[idx] = pv;
}

extern "C" void kernel_launch(void* const* d_in, const int* in_sizes, int n_in,
                              void* d_out, int out_size) {
    const float* logits = (const float*)d_in[0];   // [B*N, C]
    const float* reg    = (const float*)d_in[1];   // [B*N, C*4]
    const float* props  = (const float*)d_in[2];   // [B, N, 4]
    const float* ml     = (const float*)d_in[3];   // [B, K, C, M, M]
    float* out = (float*)d_out;

    k_softmax<<<(Bn*Nn/2*32 + 255)/256, 256>>>(logits);
    k_nms<<<Bn*CR, 128>>>(reg, props);
    k_topk<<<Bn, 512>>>(out);
    k_mask<<<(Bn*Kn*(MM/2) + 255)/256, 256>>>(ml, out);
}

// round 12
// speedup vs baseline: 1.1741x; 1.0653x over previous
#include <cuda_runtime.h>
#include <math.h>

// Problem constants (match reference)
#define Bn 8
#define Nn 1000
#define Cn 81
#define CR (Cn-1)
#define Kn 100
#define Mn 28
#define MM (Mn*Mn)
#define IMG_W 1216.0f
#define IMG_H 800.0f
#define SCORE_THRESH 0.05f
#define NMS_THRESH 0.5f
#define BBOX_CLIP 4.135166556742356f   // log(1000/16)
#define SLOT 1024                       // per-class NMS smem capacity (m <= 1000)
#define TSEL 2048                       // top-k selection smem cap
#define RANK_MAX 512                    // rank-select path cap
#define CAPI (CR*Nn)                    // per-image candidate capacity (worst case)
#define ROWS_PB 8                       // softmax rows per block (256 thr = 8 warps)

// Output layout: concat of [B,K,4] boxes, [B,K] scores, [B,K] labels, [B,K,1,M,M] masks (all f32)
#define OFF_B 0
#define OFF_S (Bn*Kn*4)
#define OFF_L (OFF_S + Bn*Kn)
#define OFF_M (OFF_L + Bn*Kn)

// ---------------- scratch (device globals; zero-initialized at load) --------
__device__ int   g_cls_m[Bn*CR];                       // above-threshold count per (b,class)
__device__ unsigned long long g_cls_key[Bn*CR*Nn];     // packed (score_bits<<32 | ~n)
__device__ int   g_img_count[Bn];                      // NMS survivors per image
__device__ float g_cand_score[Bn*CAPI];
__device__ int   g_cand_flat [Bn*CAPI];
__device__ float4 g_cand_box [Bn*CAPI];
__device__ int   g_labels[Bn*Kn];
__device__ unsigned long long g_fb_key[Bn*CAPI];       // exact fallback only

// ---------------- kernel 1: softmax + threshold-filter append ----------------
// block = 256 (8 warps); stage 8 rows (2592 floats) via coalesced float4 loads,
// then one warp per row does the shuffle softmax from smem.
__device__ __forceinline__ void append_cand(int b, int cr, int n, float s) {
    int idx = b*CR + cr;
    int p = atomicAdd(&g_cls_m[idx], 1);   // p < Nn guaranteed (one per (cr,n))
    g_cls_key[(size_t)idx*Nn + p] =
        ((unsigned long long)__float_as_uint(s) << 32)
      | (unsigned long long)(0xFFFFFFFFu - (unsigned)n);
}

__global__ void k_softmax(const float* __restrict__ logits) {
    __shared__ float tile[ROWS_PB * Cn];            // 648 floats = 2592 B
    int tid = threadIdx.x;
    int row0 = blockIdx.x * ROWS_PB;

    // coalesced staging: 162 float4 = 648 floats; block offset 2592 floats (16B-aligned)
    const float4* src = (const float4*)(logits + (size_t)row0 * Cn);
    float4* dst = (float4*)tile;
    if (tid < (ROWS_PB*Cn)/4) dst[tid] = src[tid];
    __syncthreads();

    int lane = tid & 31;
    int lr = tid >> 5;                              // local row = warp id (0..7)
    int w = row0 + lr;                              // global row

    const float* rowp = tile + lr * Cn;
    float v0 = rowp[lane];                                     // classes 0..31
    float v1 = rowp[32 + lane];                                // classes 32..63
    float v2 = (64 + lane < Cn) ? rowp[64 + lane] : -INFINITY; // classes 64..80

    float m = fmaxf(v0, fmaxf(v1, v2));
    #pragma unroll
    for (int off = 16; off > 0; off >>= 1)
        m = fmaxf(m, __shfl_xor_sync(0xFFFFFFFFu, m, off));

    float e0 = expf(v0 - m);
    float e1 = expf(v1 - m);
    float e2 = (64 + lane < Cn) ? expf(v2 - m) : 0.0f;
    float s = e0 + e1 + e2;
    #pragma unroll
    for (int off = 16; off > 0; off >>= 1)
        s += __shfl_xor_sync(0xFFFFFFFFu, s, off);

    int b = w / Nn;
    int n = w % Nn;

    float s0 = e0 / s;
    float s1 = e1 / s;
    if (lane >= 1 && s0 > SCORE_THRESH)        append_cand(b, lane - 1,  n, s0);
    if (s1 > SCORE_THRESH)                      append_cand(b, 31 + lane, n, s1);
    if (64 + lane < Cn) {
        float s2 = e2 / s;
        if (s2 > SCORE_THRESH)                  append_cand(b, 63 + lane, n, s2);
    }
}

// ---------------- kernel 2: sort -> decode -> NMS per (b,class) ----
// grid = B*CR, block = 128 (latency hiding for global gather phases)
__global__ void k_nms(const float* __restrict__ reg,
                      const float* __restrict__ props) {
    int pair = blockIdx.x;
    int b  = pair / CR;
    int cr = pair % CR;
    int cc = cr + 1;
    int tid = threadIdx.x;

    __shared__ unsigned long long key[SLOT];
    __shared__ float4 box[SLOT];
    __shared__ float  area[SLOT];
    __shared__ unsigned char keep[SLOT];
    __shared__ short sidx[SLOT];
    __shared__ int scntS, baseS;

    int m = g_cls_m[b*CR + cr];          // all threads read (same insn, pre-branch)
    if (m > Nn) m = Nn;
    if (m == 0) return;
    __syncthreads();                     // all reads complete before re-arm write
    if (tid == 0) { g_cls_m[b*CR + cr] = 0; scntS = 0; }   // re-arm for next replay

    // load pre-filtered keys
    const unsigned long long* kk = g_cls_key + (size_t)(b*CR + cr)*Nn;
    for (int i = tid; i < m; i += blockDim.x) key[i] = kk[i];

    // pad to next pow2
    int sn = 1; while (sn < m) sn <<= 1; if (sn < 2) sn = 2;
    for (int i = m + tid; i < sn; i += blockDim.x) key[i] = 0ULL;
    __syncthreads();

    // bitonic sort DESCENDING over sn keys
    for (int k = 2; k <= sn; k <<= 1) {
        for (int j = k >> 1; j > 0; j >>= 1) {
            for (int i = tid; i < sn; i += blockDim.x) {
                int ixj = i ^ j;
                if (ixj > i) {
                    unsigned long long a = key[i], bb = key[ixj];
                    bool up = ((i & k) == 0);
                    if (up ? (a < bb) : (a > bb)) { key[i] = bb; key[ixj] = a; }
                }
            }
            __syncthreads();
        }
    }

    // decode + clip boxes for the m sorted candidates
    for (int i = tid; i < m; i += blockDim.x) {
        unsigned orig = 0xFFFFFFFFu - (unsigned)(key[i] & 0xFFFFFFFFull);
        int row = b*Nn + (int)orig;
        float px1 = props[row*4+0], py1 = props[row*4+1];
        float px2 = props[row*4+2], py2 = props[row*4+3];
        float w = px2 - px1, h = py2 - py1;
        float cx = px1 + 0.5f*w, cy = py1 + 0.5f*h;
        const float* r = reg + (size_t)row*Cn*4 + cc*4;
        float dx = r[0] / 10.0f;
        float dy = r[1] / 10.0f;
        float dw = fminf(r[2] / 5.0f, BBOX_CLIP);
        float dh = fminf(r[3] / 5.0f, BBOX_CLIP);
        float pcx = dx*w + cx;
        float pcy = dy*h + cy;
        float pw = expf(dw)*w;
        float ph = expf(dh)*h;
        float x1 = pcx - 0.5f*pw, y1 = pcy - 0.5f*ph;
        float x2 = pcx + 0.5f*pw, y2 = pcy + 0.5f*ph;
        x1 = fminf(fmaxf(x1, 0.0f), IMG_W);
        y1 = fminf(fmaxf(y1, 0.0f), IMG_H);
        x2 = fminf(fmaxf(x2, 0.0f), IMG_W);
        y2 = fminf(fmaxf(y2, 0.0f), IMG_H);
        float4 bv; bv.x = x1; bv.y = y1; bv.z = x2; bv.w = y2;
        box[i] = bv;
        area[i] = (x2 - x1) * (y2 - y1);
        keep[i] = 1;
    }
    __syncthreads();

    // sequential greedy suppression
    for (int i = 0; i < m; ++i) {
        __syncthreads();
        if (!keep[i]) continue;            // uniform after barrier
        float4 bi = box[i];
        float ai = area[i];
        for (int j = i + 1 + tid; j < m; j += blockDim.x) {
            float4 bj = box[j];
            float lx = fmaxf(bi.x, bj.x);
            float ly = fmaxf(bi.y, bj.y);
            float rx = fminf(bi.z, bj.z);
            float ry = fminf(bi.w, bj.w);
            float iw = fmaxf(rx - lx, 0.0f);
            float ih = fmaxf(ry - ly, 0.0f);
            float inter = iw * ih;
            float iou = inter / (ai + area[j] - inter + 1e-9f);
            if (iou > NMS_THRESH) keep[j] = 0;
        }
    }
    __syncthreads();

    // collect survivor indices, reserve contiguous chunk in per-image list
    for (int i = tid; i < m; i += blockDim.x) {
        if (keep[i]) sidx[atomicAdd(&scntS, 1)] = (short)i;
    }
    __syncthreads();
    if (tid == 0) baseS = atomicAdd(&g_img_count[b], scntS);
    __syncthreads();
    int cnt = scntS, base = baseS;
    for (int j = tid; j < cnt; j += blockDim.x) {
        int i = sidx[j];
        int o = b*CAPI + base + j;
        g_cand_score[o] = __uint_as_float((unsigned)(key[i] >> 32));
        g_cand_flat[o]  = cr*Nn + i;     // flat index into per-class sorted layout
        g_cand_box[o]   = box[i];
    }
}

// ---------------- kernel 3: per-image top-K via radix-select + rank ----
// grid = B, block = 512; dense candidate list; shuffle-based suffix scan
__global__ void k_topk(float* __restrict__ out) {
    int b = blockIdx.x;
    int tid = threadIdx.x;
    int lane = tid & 31;
    int wid = tid >> 5;
    int V = g_img_count[b];
    if (V > CAPI) V = CAPI;
    __syncthreads();                       // ALL threads read V before re-arm
    if (tid == 0) g_img_count[b] = 0;      // re-arm for next replay

    __shared__ int hist[4096];       // 12-bit score-bit bins
    __shared__ int wsum[16], wexcl[16];
    __shared__ unsigned long long skey[TSEL];
    __shared__ int spay[TSEL];
    __shared__ int p_sh, nsel_sh, cc_sh;

    for (int i = tid; i < 4096; i += 512) hist[i] = 0;
    if (tid == 0) { p_sh = 0; cc_sh = 0; }
    __syncthreads();

    // pass 1: histogram top-12 score bits (dense, coalesced)
    for (int j = tid; j < V; j += 512) {
        unsigned bits = __float_as_uint(g_cand_score[b*CAPI + j]);
        atomicAdd(&hist[bits >> 20], 1);
    }
    __syncthreads();

    // suffix sums via 2-level shuffle scan (suf_incl(t) = sum_{t'>=t} csum(t'))
    int csum = 0;
    #pragma unroll
    for (int q = 0; q < 8; ++q) csum += hist[tid*8 + q];
    int val = csum;
    #pragma unroll
    for (int off = 1; off < 32; off <<= 1) {
        int v = __shfl_down_sync(0xFFFFFFFFu, val, off);
        if (lane + off < 32) val += v;
    }
    if (lane == 0) wsum[wid] = val;      // warp total
    __syncthreads();
    if (tid < 16) {
        int t = wsum[tid];
        int sfx = t;
        #pragma unroll
        for (int off = 1; off < 16; off <<= 1) {
            int v = __shfl_down_sync(0x0000FFFFu, sfx, off);
            if (tid + off < 16) sfx += v;
        }
        wexcl[tid] = sfx - t;            // sum over warps > tid
        if (tid == 0) nsel_sh = sfx;     // grand total
    }
    __syncthreads();
    int suf_incl = val + wexcl[wid];
    int suf_excl = suf_incl - csum;
    // unique crossing thread finds pivot p = max bin with S(bin) >= K
    if (suf_excl < Kn && suf_incl >= Kn) {
        int running = suf_excl;
        for (int q = 7; q >= 0; --q) {
            int bin = tid*8 + q;
            running += hist[bin];
            if (running >= Kn) { p_sh = bin; nsel_sh = running; break; }
        }
    }
    __syncthreads();
    int p = p_sh;
    int nsel = nsel_sh;

    if (nsel <= TSEL) {
        // pass 2: compact selected candidates (dense, coalesced)
        for (int j = tid; j < V; j += 512) {
            int o = b*CAPI + j;
            unsigned bits = __float_as_uint(g_cand_score[o]);
            if ((int)(bits >> 20) >= p) {
                int pos = atomicAdd(&cc_sh, 1);
                unsigned flat = (unsigned)g_cand_flat[o];
                skey[pos] = ((unsigned long long)bits << 17)
                          | (unsigned long long)(0x1FFFFu - flat);
                spay[pos] = j;
            }
        }
        __syncthreads();

        if (nsel <= RANK_MAX) {
            // rank-based selection: keys unique -> exact permutation
            if (tid < nsel) {
                unsigned long long mykey = skey[tid];
                int rank = 0;
                for (int j = 0; j < nsel; ++j)
                    rank += (skey[j] > mykey) ? 1 : 0;
                if (rank < Kn) {
                    int d = b*Kn + rank;
                    int o = b*CAPI + spay[tid];
                    float s   = g_cand_score[o];
                    int flat  = g_cand_flat[o];
                    int lab   = flat / Nn + 1;
                    float4 bx = g_cand_box[o];
                    out[OFF_B + d*4 + 0] = bx.x;
                    out[OFF_B + d*4 + 1] = bx.y;
                    out[OFF_B + d*4 + 2] = bx.z;
                    out[OFF_B + d*4 + 3] = bx.w;
                    out[OFF_S + d] = s;
                    out[OFF_L + d] = (float)lab;
                    g_labels[d] = lab;
                }
            }
            // zero-fill slots [nsel, K)
            if (tid >= nsel && tid < Kn) {
                int d = b*Kn + tid;
                out[OFF_B + d*4 + 0] = 0.0f;
                out[OFF_B + d*4 + 1] = 0.0f;
                out[OFF_B + d*4 + 2] = 0.0f;
                out[OFF_B + d*4 + 3] = 0.0f;
                out[OFF_S + d] = 0.0f;
                out[OFF_L + d] = 0.0f;
                g_labels[d] = 0;
            }
            return;
        }

        // bitonic path for larger nsel
        int sn = 1; while (sn < nsel) sn <<= 1; if (sn < 2) sn = 2;
        for (int i = nsel + tid; i < sn; i += 512) skey[i] = 0ULL;
        __syncthreads();
        for (int k = 2; k <= sn; k <<= 1) {
            for (int j = k >> 1; j > 0; j >>= 1) {
                for (int i = tid; i < sn; i += 512) {
                    int ixj = i ^ j;
                    if (ixj > i) {
                        unsigned long long a = skey[i], bb = skey[ixj];
                        bool up = ((i & k) == 0);
                        if (up ? (a < bb) : (a > bb)) {
                            skey[i] = bb; skey[ixj] = a;
                            int t2 = spay[i]; spay[i] = spay[ixj]; spay[ixj] = t2;
                        }
                    }
                }
                __syncthreads();
            }
        }
        if (tid < Kn) {
            int d = b*Kn + tid;
            unsigned long long v = skey[tid];
            if (tid < nsel && v != 0ULL) {
                int o = b*CAPI + spay[tid];
                float s   = g_cand_score[o];
                int flat  = g_cand_flat[o];
                int lab   = flat / Nn + 1;
                float4 bx = g_cand_box[o];
                out[OFF_B + d*4 + 0] = bx.x;
                out[OFF_B + d*4 + 1] = bx.y;
                out[OFF_B + d*4 + 2] = bx.z;
                out[OFF_B + d*4 + 3] = bx.w;
                out[OFF_S + d] = s;
                out[OFF_L + d] = (float)lab;
                g_labels[d] = lab;
            } else {
                out[OFF_B + d*4 + 0] = 0.0f;
                out[OFF_B + d*4 + 1] = 0.0f;
                out[OFF_B + d*4 + 2] = 0.0f;
                out[OFF_B + d*4 + 3] = 0.0f;
                out[OFF_S + d] = 0.0f;
                out[OFF_L + d] = 0.0f;
                g_labels[d] = 0;
            }
        }
        return;
    }

    // ---------- exact fallback (pathological tie storm): destructive argmax ----------
    for (int j = tid; j < V; j += 512) {
        int o = b*CAPI + j;
        unsigned bits = __float_as_uint(g_cand_score[o]);
        unsigned flat = (unsigned)g_cand_flat[o];
        g_fb_key[o] = ((unsigned long long)bits << 17)
                    | (unsigned long long)(0x1FFFFu - flat);
    }
    __syncthreads();
    __shared__ unsigned long long rk[512];
    __shared__ int ri[512];
    for (int k = 0; k < Kn; ++k) {
        unsigned long long bk = 0ULL; int bj = -1;
        for (int j = tid; j < V; j += 512) {
            unsigned long long v = g_fb_key[b*CAPI + j];
            if (v > bk) { bk = v; bj = j; }
        }
        rk[tid] = bk; ri[tid] = bj;
        __syncthreads();
        for (int s = 256; s > 0; s >>= 1) {
            if (tid < s && rk[tid+s] > rk[tid]) { rk[tid] = rk[tid+s]; ri[tid] = ri[tid+s]; }
            __syncthreads();
        }
        if (tid == 0) {
            int d = b*Kn + k;
            if (rk[0] != 0ULL) {
                int o = b*CAPI + ri[0];
                float s  = g_cand_score[o];
                int flat = g_cand_flat[o];
                int lab  = flat / Nn + 1;
                float4 bx = g_cand_box[o];
                out[OFF_B + d*4 + 0] = bx.x;
                out[OFF_B + d*4 + 1] = bx.y;
                out[OFF_B + d*4 + 2] = bx.z;
                out[OFF_B + d*4 + 3] = bx.w;
                out[OFF_S + d] = s;
                out[OFF_L + d] = (float)lab;
                g_labels[d] = lab;
                g_fb_key[o] = 0ULL;
            } else {
                out[OFF_B + d*4 + 0] = 0.0f;
                out[OFF_B + d*4 + 1] = 0.0f;
                out[OFF_B + d*4 + 2] = 0.0f;
                out[OFF_B + d*4 + 3] = 0.0f;
                out[OFF_S + d] = 0.0f;
                out[OFF_L + d] = 0.0f;
                g_labels[d] = 0;
            }
        }
        __syncthreads();
    }
}

// ---------------- kernel 4: mask gather + sigmoid, 1 float4/thread ----------
// grid = ceil(800*196/256), block = 256; no smem, no barriers
__global__ void k_mask(const float* __restrict__ ml, float* __restrict__ out) {
    const int Q4 = MM/4;                 // 196 float4 per det
    int idx = blockIdx.x * blockDim.x + threadIdx.x;
    if (idx >= Bn*Kn*Q4) return;
    int d = idx / Q4;
    int q = idx - d*Q4;
    int lab = g_labels[d];               // L2-broadcast across the 196 threads of det d
    float4 x = ((const float4*)(ml + ((size_t)d*Cn + lab)*MM))[q];
    float4 pv;
    pv.x = (x.x >= 0.0f) ? 1.0f/(1.0f + expf(-x.x)) : expf(x.x)/(1.0f + expf(x.x));
    pv.y = (x.y >= 0.0f) ? 1.0f/(1.0f + expf(-x.y)) : expf(x.y)/(1.0f + expf(x.y));
    pv.z = (x.z >= 0.0f) ? 1.0f/(1.0f + expf(-x.z)) : expf(x.z)/(1.0f + expf(x.z));
    pv.w = (x.w >= 0.0f) ? 1.0f/(1.0f + expf(-x.w)) : expf(x.w)/(1.0f + expf(x.w));
    ((float4*)(out + OFF_M))[idx] = pv;
}

extern "C" void kernel_launch(void* const* d_in, const int* in_sizes, int n_in,
                              void* d_out, int out_size) {
    const float* logits = (const float*)d_in[0];   // [B*N, C]
    const float* reg    = (const float*)d_in[1];   // [B*N, C*4]
    const float* props  = (const float*)d_in[2];   // [B, N, 4]
    const float* ml     = (const float*)d_in[3];   // [B, K, C, M, M]
    float* out = (float*)d_out;

    k_softmax<<<Bn*Nn/ROWS_PB, 256>>>(logits);
    k_nms<<<Bn*CR, 128>>>(reg, props);
    k_topk<<<Bn, 512>>>(out);
    k_mask<<<(Bn*Kn*(MM/4) + 255)/256, 256>>>(ml, out);
}